// round 4
// baseline (speedup 1.0000x reference)
#include <cuda_runtime.h>
#include <math.h>

// Problem constants (shapes are fixed by the reference)
#define BB    4
#define SS    16
#define DIMM  4096
#define NHH   32
#define NKVV  8
#define HDD   128
#define MAXPP 4096
#define STARTP 2048
#define LCTX  2064   // STARTP + SS

// ---------------------------------------------------------------------------
// Device scratch (no allocations allowed)
// ---------------------------------------------------------------------------
__device__ float g_q[BB*SS*NHH*HDD];        // 262144  row=(b*16+s), col=h*128+d
__device__ float g_k[BB*SS*NKVV*HDD];       // 65536   row=(b*16+s), col=kvh*128+d
__device__ float g_v[BB*SS*NKVV*HDD];       // 65536
__device__ float g_scores[(size_t)BB*NHH*SS*LCTX]; // 4,227,072 floats (~17MB)
__device__ float g_attn[BB*SS*NHH*HDD];     // 262144  row=(b*16+s), col=h*128+d

// ---------------------------------------------------------------------------
// Zero scratch + output (needed because GEMM/PV accumulate with atomics)
// ---------------------------------------------------------------------------
__global__ void zero_kernel(float* __restrict__ dout) {
    int i = blockIdx.x * blockDim.x + threadIdx.x;   // grid covers 262144
    if (i < BB*SS*NHH*HDD) { g_q[i] = 0.f; g_attn[i] = 0.f; dout[i] = 0.f; }
    if (i < BB*SS*NKVV*HDD) { g_k[i] = 0.f; g_v[i] = 0.f; }
}

// ---------------------------------------------------------------------------
// Tiled fp32 GEMM: C[64 x N] += A[64 x 4096] * W[4096 x N]
// BM=64, BN=128, BK=16, 256 threads, 4x8 register tile, split-K over gridDim.y
// a_sel: 0 -> Aext (x), 1 -> g_attn
// c_sel: 0 -> g_q, 1 -> g_k, 2 -> g_v, 3 -> Cext (d_out)
// ---------------------------------------------------------------------------
__global__ __launch_bounds__(256) void gemm64(
    const float* __restrict__ Aext, const float* __restrict__ W,
    float* __restrict__ Cext, int a_sel, int c_sel, int N)
{
    const float* A = a_sel ? (const float*)g_attn : Aext;
    float* C;
    switch (c_sel) {
        case 0: C = g_q; break;
        case 1: C = g_k; break;
        case 2: C = g_v; break;
        default: C = Cext; break;
    }

    __shared__ float As[16][64];
    __shared__ float Bs[16][128];

    const int n0 = blockIdx.x * 128;
    const int kChunk = DIMM / 4;               // gridDim.y == 4
    const int k0 = blockIdx.y * kChunk;
    const int t  = threadIdx.x;
    const int tx = t & 15, ty = t >> 4;

    float acc[4][8];
    #pragma unroll
    for (int i = 0; i < 4; i++)
        #pragma unroll
        for (int j = 0; j < 8; j++) acc[i][j] = 0.f;

    for (int kk = 0; kk < kChunk; kk += 16) {
        // Load A tile: 64 rows x 16 k (one float4 per thread), store transposed
        {
            int row = t >> 2, kq = t & 3;
            float4 a4 = *(const float4*)(A + (size_t)row * DIMM + k0 + kk + kq * 4);
            As[kq*4+0][row] = a4.x;
            As[kq*4+1][row] = a4.y;
            As[kq*4+2][row] = a4.z;
            As[kq*4+3][row] = a4.w;
        }
        // Load B tile: 16 k-rows x 128 cols (two float4 per thread)
        #pragma unroll
        for (int r = 0; r < 2; r++) {
            int f  = t * 2 + r;
            int kr = f >> 5;
            int nq = f & 31;
            *(float4*)&Bs[kr][nq*4] =
                *(const float4*)(W + (size_t)(k0 + kk + kr) * N + n0 + nq * 4);
        }
        __syncthreads();

        #pragma unroll
        for (int k = 0; k < 16; k++) {
            float4 a  = *(const float4*)&As[k][ty*4];
            float4 b0 = *(const float4*)&Bs[k][tx*8];
            float4 b1 = *(const float4*)&Bs[k][tx*8+4];
            float av[4] = {a.x, a.y, a.z, a.w};
            float bv[8] = {b0.x, b0.y, b0.z, b0.w, b1.x, b1.y, b1.z, b1.w};
            #pragma unroll
            for (int i = 0; i < 4; i++)
                #pragma unroll
                for (int j = 0; j < 8; j++)
                    acc[i][j] = fmaf(av[i], bv[j], acc[i][j]);
        }
        __syncthreads();
    }

    #pragma unroll
    for (int i = 0; i < 4; i++)
        #pragma unroll
        for (int j = 0; j < 8; j++)
            atomicAdd(&C[(size_t)(ty*4 + i) * N + n0 + tx*8 + j], acc[i][j]);
}

// ---------------------------------------------------------------------------
// RoPE on g_q (all 32 heads) and g_k (8 kv heads), in place.
// One thread per (row, head, j) pair; d = 2j, 2j+1.
// ---------------------------------------------------------------------------
__global__ void rope_kernel(const float* __restrict__ fc, const float* __restrict__ fs) {
    int idx = blockIdx.x * blockDim.x + threadIdx.x;
    const int QP = BB*SS*NHH*64;   // 131072
    const int KP = BB*SS*NKVV*64;  // 32768
    if (idx >= QP + KP) return;

    float* ptr;
    int s, j;
    if (idx < QP) {
        int row = idx >> 11;       // /(32*64)
        int rem = idx & 2047;
        int h = rem >> 6; j = rem & 63;
        s = row & 15;
        ptr = g_q + (size_t)row * 4096 + h * 128 + j * 2;
    } else {
        int i2 = idx - QP;
        int row = i2 >> 9;         // /(8*64)
        int rem = i2 & 511;
        int h = rem >> 6; j = rem & 63;
        s = row & 15;
        ptr = g_k + (size_t)row * 1024 + h * 128 + j * 2;
    }
    float c  = fc[s * 64 + j];
    float sn = fs[s * 64 + j];
    float x0 = ptr[0], x1 = ptr[1];
    ptr[0] = x0 * c - x1 * sn;
    ptr[1] = x0 * sn + x1 * c;
}

// ---------------------------------------------------------------------------
// Scores: S[b,h,s,l] = (q . k) / sqrt(HD)
// Block = (64-key tile, bh). 128 threads; 4q x 2k register tile, d reduced via
// float4 loads from smem (ks rows padded to 132 floats -> conflict-free).
// Keys: cache_k for l < 2048, g_k (post-RoPE) for l in [2048, 2064).
// ---------------------------------------------------------------------------
__global__ __launch_bounds__(128) void scores_kernel(const float* __restrict__ cache_k) {
    const int bh  = blockIdx.y;
    const int b   = bh >> 5, h = bh & 31, kvh = h >> 2;
    const int l0  = blockIdx.x * 64;

    __shared__ float qs[16][128];
    __shared__ float ks[64][132];

    const int t = threadIdx.x;

    #pragma unroll
    for (int r = 0; r < 4; r++) {
        int f = t + r * 128; int s = f >> 5, dq = f & 31;
        *(float4*)&qs[s][dq*4] =
            *(const float4*)&g_q[(size_t)(b*16 + s) * 4096 + h * 128 + dq * 4];
    }
    #pragma unroll
    for (int r = 0; r < 16; r++) {
        int f = t + r * 128; int i = f >> 5, dq = f & 31;
        int l = l0 + i;
        float4 v = make_float4(0.f, 0.f, 0.f, 0.f);
        if (l < STARTP)
            v = *(const float4*)&cache_k[(((size_t)b * MAXPP + l) * NKVV + kvh) * HDD + dq * 4];
        else if (l < LCTX)
            v = *(const float4*)&g_k[(size_t)(b*16 + (l - STARTP)) * 1024 + kvh * 128 + dq * 4];
        *(float4*)&ks[i][dq*4] = v;
    }
    __syncthreads();

    const int tq = t >> 5;       // warp id: 0..3 -> 4 query rows each
    const int tk = t & 31;       // keys tk and tk+32
    float acc0[4] = {0.f,0.f,0.f,0.f};
    float acc1[4] = {0.f,0.f,0.f,0.f};

    #pragma unroll 8
    for (int d = 0; d < 128; d += 4) {
        float4 k0 = *(const float4*)&ks[tk][d];
        float4 k1 = *(const float4*)&ks[tk + 32][d];
        #pragma unroll
        for (int i = 0; i < 4; i++) {
            float4 a = *(const float4*)&qs[tq*4 + i][d];
            acc0[i] += a.x*k0.x + a.y*k0.y + a.z*k0.z + a.w*k0.w;
            acc1[i] += a.x*k1.x + a.y*k1.y + a.z*k1.z + a.w*k1.w;
        }
    }

    const float sc = 0.08838834764831845f;  // 1/sqrt(128)
    const int la = l0 + tk, lb = l0 + tk + 32;
    #pragma unroll
    for (int i = 0; i < 4; i++) {
        size_t rb = ((size_t)bh * 16 + tq*4 + i) * LCTX;
        if (la < LCTX) g_scores[rb + la] = acc0[i] * sc;
        if (lb < LCTX) g_scores[rb + lb] = acc1[i] * sc;
    }
}

// ---------------------------------------------------------------------------
// Row softmax over L=2064, one block (256 threads) per (b,h,s) row.
// ---------------------------------------------------------------------------
__global__ __launch_bounds__(256) void softmax_kernel() {
    const int row = blockIdx.x;           // 0..2047
    float* p = g_scores + (size_t)row * LCTX;
    const int t = threadIdx.x;
    __shared__ float red[8];

    float vals[9];
    int nv = 0;
    float m = -1e30f;
    for (int i = t; i < LCTX; i += 256) { float v = p[i]; vals[nv++] = v; m = fmaxf(m, v); }

    #pragma unroll
    for (int o = 16; o; o >>= 1) m = fmaxf(m, __shfl_xor_sync(0xffffffffu, m, o));
    if ((t & 31) == 0) red[t >> 5] = m;
    __syncthreads();
    float mm = red[0];
    #pragma unroll
    for (int w = 1; w < 8; w++) mm = fmaxf(mm, red[w]);
    __syncthreads();

    float sum = 0.f;
    for (int j = 0; j < nv; j++) { vals[j] = expf(vals[j] - mm); sum += vals[j]; }
    #pragma unroll
    for (int o = 16; o; o >>= 1) sum += __shfl_xor_sync(0xffffffffu, sum, o);
    if ((t & 31) == 0) red[t >> 5] = sum;
    __syncthreads();
    float tot = 0.f;
    #pragma unroll
    for (int w = 0; w < 8; w++) tot += red[w];

    float inv = 1.0f / tot;
    nv = 0;
    for (int i = t; i < LCTX; i += 256) p[i] = vals[nv++] * inv;
}

// ---------------------------------------------------------------------------
// out[b,h,s,d] = sum_l P[b,h,s,l] * V[b,l,kvh,d]
// Block = (split, bh); each split handles 11 of 33 64-key tiles and
// atomically accumulates into g_attn (zeroed each call).
// ---------------------------------------------------------------------------
__global__ __launch_bounds__(128) void pv_kernel(const float* __restrict__ cache_v) {
    const int bh = blockIdx.y;
    const int b = bh >> 5, h = bh & 31, kvh = h >> 2;
    const int split = blockIdx.x;   // 0..2

    __shared__ float Ps[16][68];
    __shared__ float Vs[64][132];

    const int t = threadIdx.x;
    const int sg = t >> 5, dg = t & 31;   // 4 query rows, float4 of d each
    float acc[4][4];
    #pragma unroll
    for (int i = 0; i < 4; i++)
        #pragma unroll
        for (int j = 0; j < 4; j++) acc[i][j] = 0.f;

    for (int tt = split * 11; tt < split * 11 + 11; tt++) {
        const int l0 = tt * 64;
        // P tile: 16 x 64
        #pragma unroll
        for (int r = 0; r < 2; r++) {
            int f = t + r * 128; int s = f >> 4, lq = f & 15;
            int l = l0 + lq * 4;
            float4 v = make_float4(0.f, 0.f, 0.f, 0.f);
            if (l < LCTX)   // LCTX % 4 == 0: a float4 is either fully valid or fully OOB
                v = *(const float4*)&g_scores[((size_t)bh * 16 + s) * LCTX + l];
            *(float4*)&Ps[s][lq*4] = v;
        }
        // V tile: 64 x 128
        #pragma unroll
        for (int r = 0; r < 16; r++) {
            int f = t + r * 128; int i = f >> 5, dq = f & 31;
            int l = l0 + i;
            float4 v = make_float4(0.f, 0.f, 0.f, 0.f);
            if (l < STARTP)
                v = *(const float4*)&cache_v[(((size_t)b * MAXPP + l) * NKVV + kvh) * HDD + dq * 4];
            else if (l < LCTX)
                v = *(const float4*)&g_v[(size_t)(b*16 + (l - STARTP)) * 1024 + kvh * 128 + dq * 4];
            *(float4*)&Vs[i][dq*4] = v;
        }
        __syncthreads();

        #pragma unroll 8
        for (int l = 0; l < 64; l++) {
            float4 v = *(const float4*)&Vs[l][dg*4];
            #pragma unroll
            for (int i = 0; i < 4; i++) {
                float pp = Ps[sg*4 + i][l];
                acc[i][0] = fmaf(pp, v.x, acc[i][0]);
                acc[i][1] = fmaf(pp, v.y, acc[i][1]);
                acc[i][2] = fmaf(pp, v.z, acc[i][2]);
                acc[i][3] = fmaf(pp, v.w, acc[i][3]);
            }
        }
        __syncthreads();
    }

    #pragma unroll
    for (int i = 0; i < 4; i++) {
        int s = sg * 4 + i;
        float* dst = &g_attn[(size_t)(b*16 + s) * 4096 + h * 128 + dg * 4];
        atomicAdd(dst + 0, acc[i][0]);
        atomicAdd(dst + 1, acc[i][1]);
        atomicAdd(dst + 2, acc[i][2]);
        atomicAdd(dst + 3, acc[i][3]);
    }
}

// ---------------------------------------------------------------------------
// Launch
// ---------------------------------------------------------------------------
extern "C" void kernel_launch(void* const* d_in, const int* in_sizes, int n_in,
                              void* d_out, int out_size) {
    const float* x       = (const float*)d_in[0];
    const float* fc      = (const float*)d_in[1];
    const float* fs      = (const float*)d_in[2];
    const float* cache_k = (const float*)d_in[3];
    const float* cache_v = (const float*)d_in[4];
    const float* Wq      = (const float*)d_in[5];
    const float* Wk      = (const float*)d_in[6];
    const float* Wv      = (const float*)d_in[7];
    const float* Wo      = (const float*)d_in[8];
    float* out = (float*)d_out;
    (void)in_sizes; (void)n_in; (void)out_size;   // shapes fixed; start_pos == 2048

    zero_kernel<<<1024, 256>>>(out);

    // QKV projections (split-K=4, atomic accumulate)
    gemm64<<<dim3(32, 4), 256>>>(x, Wq, nullptr, 0, 0, NHH * HDD);   // -> g_q
    gemm64<<<dim3( 8, 4), 256>>>(x, Wk, nullptr, 0, 1, NKVV * HDD);  // -> g_k
    gemm64<<<dim3( 8, 4), 256>>>(x, Wv, nullptr, 0, 2, NKVV * HDD);  // -> g_v

    rope_kernel<<<640, 256>>>(fc, fs);

    scores_kernel<<<dim3(33, 128), 128>>>(cache_k);
    softmax_kernel<<<2048, 256>>>();
    pv_kernel<<<dim3(3, 128), 128>>>(cache_v);

    // Output projection -> d_out
    gemm64<<<dim3(32, 4), 256>>>(nullptr, Wo, out, 1, 3, DIMM);
}

// round 5
// speedup vs baseline: 1.8648x; 1.8648x over previous
#include <cuda_runtime.h>
#include <math.h>

// Problem constants (shapes fixed by the reference)
#define BB    4
#define SS    16
#define DIMM  4096
#define NHH   32
#define NKVV  8
#define HDD   128
#define MAXPP 4096
#define STARTP 2048
#define LCTX  2064   // STARTP + SS
#define SPLITK 16
#define KCHUNK (DIMM / SPLITK)   // 256 -> 16 BK=16 iterations per block

typedef unsigned long long ull;

// ---------------------------------------------------------------------------
// Packed f32x2 helpers (B300 FFMA2 path — only reachable via explicit PTX)
// ---------------------------------------------------------------------------
__device__ __forceinline__ ull pack2(float lo, float hi) {
    ull r; asm("mov.b64 %0, {%1, %2};" : "=l"(r) : "f"(lo), "f"(hi)); return r;
}
__device__ __forceinline__ void ffma2(ull &d, ull a, ull b) {
    asm("fma.rn.f32x2 %0, %1, %2, %0;" : "+l"(d) : "l"(a), "l"(b));
}
__device__ __forceinline__ void unpack2(ull v, float &lo, float &hi) {
    asm("mov.b64 {%0, %1}, %2;" : "=f"(lo), "=f"(hi) : "l"(v));
}

// ---------------------------------------------------------------------------
// Device scratch (no allocations allowed)
// ---------------------------------------------------------------------------
__device__ float g_q[BB*SS*NHH*HDD];        // row=(b*16+s), col=h*128+d
__device__ float g_k[BB*SS*NKVV*HDD];       // row=(b*16+s), col=kvh*128+d
__device__ float g_v[BB*SS*NKVV*HDD];
__device__ float g_scores[(size_t)BB*NHH*SS*LCTX]; // ~17MB
__device__ float g_attn[BB*SS*NHH*HDD];     // row=(b*16+s), col=h*128+d

// ---------------------------------------------------------------------------
// Zero scratch + output (GEMM/PV accumulate with atomics)
// ---------------------------------------------------------------------------
__global__ void zero_kernel(float* __restrict__ dout) {
    int i = blockIdx.x * blockDim.x + threadIdx.x;   // grid covers 262144
    if (i < BB*SS*NHH*HDD) { g_q[i] = 0.f; g_attn[i] = 0.f; dout[i] = 0.f; }
    if (i < BB*SS*NKVV*HDD) { g_k[i] = 0.f; g_v[i] = 0.f; }
}

// ---------------------------------------------------------------------------
// Tiled fp32 GEMM with split-K=16, register double-buffering, FFMA2.
// C[64 x N] += A[64 x 4096] * W[4096 x N]
// mode 0: fused QKV (bx<32 -> Wq->g_q, bx<40 -> Wk->g_k, else Wv->g_v), A=x
// mode 1: Wo -> d_out, A=g_attn
// ---------------------------------------------------------------------------
__global__ __launch_bounds__(256) void gemm64(
    const float* __restrict__ Aext,
    const float* __restrict__ W0, const float* __restrict__ W1,
    const float* __restrict__ W2,
    float* __restrict__ Cout, int mode)
{
    const float* A; const float* W; float* C; int N, n0;
    const int bx = blockIdx.x;
    if (mode == 0) {
        A = Aext;
        if (bx < 32)      { W = W0; C = g_q; N = 4096; n0 = bx * 128; }
        else if (bx < 40) { W = W1; C = g_k; N = 1024; n0 = (bx - 32) * 128; }
        else              { W = W2; C = g_v; N = 1024; n0 = (bx - 40) * 128; }
    } else {
        A = g_attn; W = W0; C = Cout; N = 4096; n0 = bx * 128;
    }
    const int k0 = blockIdx.y * KCHUNK;

    __shared__ float As[16][64];
    __shared__ float Bs[16][128];

    const int t  = threadIdx.x;
    const int tx = t & 15, ty = t >> 4;
    const int arow = t >> 2, akq = t & 3;
    const int f0 = t * 2, f1 = t * 2 + 1;
    const int kr0 = f0 >> 5, nq0 = f0 & 31;
    const int kr1 = f1 >> 5, nq1 = f1 & 31;

    ull acc2[4][4];
    #pragma unroll
    for (int i = 0; i < 4; i++)
        #pragma unroll
        for (int j = 0; j < 4; j++) acc2[i][j] = 0ull;

    // Prologue: preload first tile into registers
    float4 aN = *(const float4*)(A + (size_t)arow * DIMM + k0 + akq * 4);
    float4 bN0 = *(const float4*)(W + (size_t)(k0 + kr0) * N + n0 + nq0 * 4);
    float4 bN1 = *(const float4*)(W + (size_t)(k0 + kr1) * N + n0 + nq1 * 4);

    #pragma unroll 1
    for (int it = 0; it < KCHUNK / 16; it++) {
        As[akq*4+0][arow] = aN.x;
        As[akq*4+1][arow] = aN.y;
        As[akq*4+2][arow] = aN.z;
        As[akq*4+3][arow] = aN.w;
        *(float4*)&Bs[kr0][nq0*4] = bN0;
        *(float4*)&Bs[kr1][nq1*4] = bN1;
        __syncthreads();

        if (it + 1 < KCHUNK / 16) {   // overlap next tile's gmem loads with compute
            const int kk = k0 + (it + 1) * 16;
            aN  = *(const float4*)(A + (size_t)arow * DIMM + kk + akq * 4);
            bN0 = *(const float4*)(W + (size_t)(kk + kr0) * N + n0 + nq0 * 4);
            bN1 = *(const float4*)(W + (size_t)(kk + kr1) * N + n0 + nq1 * 4);
        }

        #pragma unroll
        for (int k = 0; k < 16; k++) {
            float4 a  = *(const float4*)&As[k][ty*4];
            float4 b0 = *(const float4*)&Bs[k][tx*8];
            float4 b1 = *(const float4*)&Bs[k][tx*8+4];
            ull bp0 = pack2(b0.x, b0.y), bp1 = pack2(b0.z, b0.w);
            ull bp2 = pack2(b1.x, b1.y), bp3 = pack2(b1.z, b1.w);
            ull ap0 = pack2(a.x, a.x), ap1 = pack2(a.y, a.y);
            ull ap2 = pack2(a.z, a.z), ap3 = pack2(a.w, a.w);
            ffma2(acc2[0][0], ap0, bp0); ffma2(acc2[0][1], ap0, bp1);
            ffma2(acc2[0][2], ap0, bp2); ffma2(acc2[0][3], ap0, bp3);
            ffma2(acc2[1][0], ap1, bp0); ffma2(acc2[1][1], ap1, bp1);
            ffma2(acc2[1][2], ap1, bp2); ffma2(acc2[1][3], ap1, bp3);
            ffma2(acc2[2][0], ap2, bp0); ffma2(acc2[2][1], ap2, bp1);
            ffma2(acc2[2][2], ap2, bp2); ffma2(acc2[2][3], ap2, bp3);
            ffma2(acc2[3][0], ap3, bp0); ffma2(acc2[3][1], ap3, bp1);
            ffma2(acc2[3][2], ap3, bp2); ffma2(acc2[3][3], ap3, bp3);
        }
        __syncthreads();
    }

    #pragma unroll
    for (int i = 0; i < 4; i++)
        #pragma unroll
        for (int j = 0; j < 4; j++) {
            float c0, c1; unpack2(acc2[i][j], c0, c1);
            float* dst = &C[(size_t)(ty*4 + i) * N + n0 + tx*8 + 2*j];
            atomicAdd(dst + 0, c0);
            atomicAdd(dst + 1, c1);
        }
}

// ---------------------------------------------------------------------------
// RoPE on g_q and g_k, in place.
// ---------------------------------------------------------------------------
__global__ void rope_kernel(const float* __restrict__ fc, const float* __restrict__ fs) {
    int idx = blockIdx.x * blockDim.x + threadIdx.x;
    const int QP = BB*SS*NHH*64;   // 131072
    const int KP = BB*SS*NKVV*64;  // 32768
    if (idx >= QP + KP) return;

    float* ptr;
    int s, j;
    if (idx < QP) {
        int row = idx >> 11;
        int rem = idx & 2047;
        int h = rem >> 6; j = rem & 63;
        s = row & 15;
        ptr = g_q + (size_t)row * 4096 + h * 128 + j * 2;
    } else {
        int i2 = idx - QP;
        int row = i2 >> 9;
        int rem = i2 & 511;
        int h = rem >> 6; j = rem & 63;
        s = row & 15;
        ptr = g_k + (size_t)row * 1024 + h * 128 + j * 2;
    }
    float c  = fc[s * 64 + j];
    float sn = fs[s * 64 + j];
    float x0 = ptr[0], x1 = ptr[1];
    ptr[0] = x0 * c - x1 * sn;
    ptr[1] = x0 * sn + x1 * c;
}

// ---------------------------------------------------------------------------
// Scores: block = (64-key tile, b*8+kvh). K tile loaded ONCE, reused by the
// 4 query heads of the GQA group (4x less K traffic). FFMA2 dot products.
// ---------------------------------------------------------------------------
__global__ __launch_bounds__(128) void scores_kernel(const float* __restrict__ cache_k) {
    const int g   = blockIdx.y;          // 0..31  = b*8 + kvh
    const int b   = g >> 3, kvh = g & 7;
    const int l0  = blockIdx.x * 64;

    __shared__ float ks[64][132];
    __shared__ float qs[16][132];

    const int t = threadIdx.x;

    #pragma unroll
    for (int r = 0; r < 16; r++) {
        int f = t + r * 128; int i = f >> 5, dq = f & 31;
        int l = l0 + i;
        float4 v = make_float4(0.f, 0.f, 0.f, 0.f);
        if (l < STARTP)
            v = *(const float4*)&cache_k[(((size_t)b * MAXPP + l) * NKVV + kvh) * HDD + dq * 4];
        else if (l < LCTX)
            v = *(const float4*)&g_k[(size_t)(b*16 + (l - STARTP)) * 1024 + kvh * 128 + dq * 4];
        *(float4*)&ks[i][dq*4] = v;
    }

    const int tq = t >> 5;       // warp id -> 4 query rows each
    const int tk = t & 31;       // keys tk and tk+32
    const float sc = 0.08838834764831845f;  // 1/sqrt(128)
    const int la = l0 + tk, lb = l0 + tk + 32;

    for (int hl = 0; hl < 4; hl++) {
        const int h = kvh * 4 + hl;
        __syncthreads();   // hl=0: makes ks visible; hl>0: prior compute done before qs overwrite
        #pragma unroll
        for (int r = 0; r < 4; r++) {
            int f = t + r * 128; int s = f >> 5, dq = f & 31;
            *(float4*)&qs[s][dq*4] =
                *(const float4*)&g_q[(size_t)(b*16 + s) * 4096 + h * 128 + dq * 4];
        }
        __syncthreads();

        ull acc0[4] = {0ull,0ull,0ull,0ull};
        ull acc1[4] = {0ull,0ull,0ull,0ull};

        #pragma unroll 8
        for (int d = 0; d < 128; d += 4) {
            float4 k0 = *(const float4*)&ks[tk][d];
            float4 k1 = *(const float4*)&ks[tk + 32][d];
            ull k0a = pack2(k0.x, k0.y), k0b = pack2(k0.z, k0.w);
            ull k1a = pack2(k1.x, k1.y), k1b = pack2(k1.z, k1.w);
            #pragma unroll
            for (int i = 0; i < 4; i++) {
                float4 q = *(const float4*)&qs[tq*4 + i][d];
                ull qa = pack2(q.x, q.y), qb = pack2(q.z, q.w);
                ffma2(acc0[i], qa, k0a); ffma2(acc0[i], qb, k0b);
                ffma2(acc1[i], qa, k1a); ffma2(acc1[i], qb, k1b);
            }
        }

        const int bh = b * 32 + h;
        #pragma unroll
        for (int i = 0; i < 4; i++) {
            size_t rb = ((size_t)bh * 16 + tq*4 + i) * LCTX;
            float lo, hi;
            unpack2(acc0[i], lo, hi); if (la < LCTX) g_scores[rb + la] = (lo + hi) * sc;
            unpack2(acc1[i], lo, hi); if (lb < LCTX) g_scores[rb + lb] = (lo + hi) * sc;
        }
    }
}

// ---------------------------------------------------------------------------
// Row softmax over L=2064, one block (256 threads) per (b,h,s) row.
// ---------------------------------------------------------------------------
__global__ __launch_bounds__(256) void softmax_kernel() {
    const int row = blockIdx.x;           // 0..2047
    float* p = g_scores + (size_t)row * LCTX;
    const int t = threadIdx.x;
    __shared__ float red[8];

    float vals[9];
    int nv = 0;
    float m = -1e30f;
    for (int i = t; i < LCTX; i += 256) { float v = p[i]; vals[nv++] = v; m = fmaxf(m, v); }

    #pragma unroll
    for (int o = 16; o; o >>= 1) m = fmaxf(m, __shfl_xor_sync(0xffffffffu, m, o));
    if ((t & 31) == 0) red[t >> 5] = m;
    __syncthreads();
    float mm = red[0];
    #pragma unroll
    for (int w = 1; w < 8; w++) mm = fmaxf(mm, red[w]);
    __syncthreads();

    float sum = 0.f;
    for (int j = 0; j < nv; j++) { vals[j] = __expf(vals[j] - mm); sum += vals[j]; }
    #pragma unroll
    for (int o = 16; o; o >>= 1) sum += __shfl_xor_sync(0xffffffffu, sum, o);
    if ((t & 31) == 0) red[t >> 5] = sum;
    __syncthreads();
    float tot = 0.f;
    #pragma unroll
    for (int w = 0; w < 8; w++) tot += red[w];

    float inv = 1.0f / tot;
    nv = 0;
    for (int i = t; i < LCTX; i += 256) p[i] = vals[nv++] * inv;
}

// ---------------------------------------------------------------------------
// PV: block = (split 0..10, b*8+kvh). Each split does 3 of the 33 64-key
// tiles. V tile loaded ONCE per tile and reused by the 4 GQA heads.
// Atomic accumulation into g_attn. FFMA2 inner loop.
// ---------------------------------------------------------------------------
__global__ __launch_bounds__(128) void pv_kernel(const float* __restrict__ cache_v) {
    const int g = blockIdx.y;            // b*8 + kvh
    const int b = g >> 3, kvh = g & 7;
    const int split = blockIdx.x;        // 0..10

    __shared__ float Vs[64][128];
    __shared__ float Ps[16][64];

    const int t = threadIdx.x;
    const int sg = t >> 5, dg = t & 31;  // 4 query rows, float4 of d each

    ull acc2[4][4][2];                   // [head][q][d-pair]
    #pragma unroll
    for (int hl = 0; hl < 4; hl++)
        #pragma unroll
        for (int i = 0; i < 4; i++) { acc2[hl][i][0] = 0ull; acc2[hl][i][1] = 0ull; }

    for (int tt = split * 3; tt < split * 3 + 3; tt++) {
        const int l0 = tt * 64;
        __syncthreads();                 // prior compute done before Vs/Ps overwrite
        #pragma unroll
        for (int r = 0; r < 16; r++) {
            int f = t + r * 128; int i = f >> 5, dq = f & 31;
            int l = l0 + i;
            float4 v = make_float4(0.f, 0.f, 0.f, 0.f);
            if (l < STARTP)
                v = *(const float4*)&cache_v[(((size_t)b * MAXPP + l) * NKVV + kvh) * HDD + dq * 4];
            else if (l < LCTX)
                v = *(const float4*)&g_v[(size_t)(b*16 + (l - STARTP)) * 1024 + kvh * 128 + dq * 4];
            *(float4*)&Vs[i][dq*4] = v;
        }

        for (int hl = 0; hl < 4; hl++) {
            if (hl) __syncthreads();     // prev head compute done before Ps overwrite
            const int bh = b * 32 + kvh * 4 + hl;
            #pragma unroll
            for (int r = 0; r < 2; r++) {
                int f = t + r * 128; int s = f >> 4, lq = f & 15;
                int l = l0 + lq * 4;
                float4 v = make_float4(0.f, 0.f, 0.f, 0.f);
                if (l < LCTX)   // LCTX % 4 == 0
                    v = *(const float4*)&g_scores[((size_t)bh * 16 + s) * LCTX + l];
                *(float4*)&Ps[s][lq*4] = v;
            }
            __syncthreads();

            #pragma unroll 4
            for (int l = 0; l < 64; l++) {
                ull v01 = *(const ull*)&Vs[l][dg*4];
                ull v23 = *(const ull*)&Vs[l][dg*4 + 2];
                #pragma unroll
                for (int i = 0; i < 4; i++) {
                    float pp = Ps[sg*4 + i][l];
                    ull p2 = pack2(pp, pp);
                    ffma2(acc2[hl][i][0], p2, v01);
                    ffma2(acc2[hl][i][1], p2, v23);
                }
            }
        }
    }

    #pragma unroll
    for (int hl = 0; hl < 4; hl++) {
        const int h = kvh * 4 + hl;
        #pragma unroll
        for (int i = 0; i < 4; i++) {
            int s = sg * 4 + i;
            float* dst = &g_attn[(size_t)(b*16 + s) * 4096 + h * 128 + dg * 4];
            float c0, c1;
            unpack2(acc2[hl][i][0], c0, c1);
            atomicAdd(dst + 0, c0);
            atomicAdd(dst + 1, c1);
            unpack2(acc2[hl][i][1], c0, c1);
            atomicAdd(dst + 2, c0);
            atomicAdd(dst + 3, c1);
        }
    }
}

// ---------------------------------------------------------------------------
// Launch
// ---------------------------------------------------------------------------
extern "C" void kernel_launch(void* const* d_in, const int* in_sizes, int n_in,
                              void* d_out, int out_size) {
    const float* x       = (const float*)d_in[0];
    const float* fc      = (const float*)d_in[1];
    const float* fs      = (const float*)d_in[2];
    const float* cache_k = (const float*)d_in[3];
    const float* cache_v = (const float*)d_in[4];
    const float* Wq      = (const float*)d_in[5];
    const float* Wk      = (const float*)d_in[6];
    const float* Wv      = (const float*)d_in[7];
    const float* Wo      = (const float*)d_in[8];
    float* out = (float*)d_out;
    (void)in_sizes; (void)n_in; (void)out_size;

    zero_kernel<<<1024, 256>>>(out);

    // Fused QKV projections (split-K=16, atomic accumulate): 48x16 = 768 blocks
    gemm64<<<dim3(48, SPLITK), 256>>>(x, Wq, Wk, Wv, nullptr, 0);

    rope_kernel<<<640, 256>>>(fc, fs);

    scores_kernel<<<dim3(33, 32), 128>>>(cache_k);
    softmax_kernel<<<2048, 256>>>();
    pv_kernel<<<dim3(11, 32), 128>>>(cache_v);

    // Output projection -> d_out: 32x16 = 512 blocks
    gemm64<<<dim3(32, SPLITK), 256>>>(nullptr, Wo, nullptr, nullptr, out, 1);
}